// round 1
// baseline (speedup 1.0000x reference)
#include <cuda_runtime.h>
#include <cstdint>

// ProdEinsumTC: out[a,b,c,d,g] = (1/3) * sum_{e,f} T1[a,b,c,d,e,f] * T2[b,c,e,f,g]
// T1: (4, 131072, 6, 3,3,3) fp32   T2: (131072, 6, 3,3,3) fp32
// Collapse (b,c) -> BC = 786432. Per bc: T1 has 4 contiguous 27-float blocks
// (one per path a, stride BC*27 apart), T2 one 27-float block, out 4x9.
//
// Strategy: tile 64 bc-pairs per 256-thread block. Stage T2 (1728 f) and
// T1 (4*1728 f) tiles via coalesced float4 loads into smem; one thread per
// (a, bc_local) computes the 3x3 (d,g) output block from 27+27 smem floats.
// Stride-27 smem access across lanes -> conflict-free (gcd(27,32)=1).

#define BC      786432          // 131072 * 6
#define TILE    64              // bc pairs per block
#define NTHREADS 256            // TILE * 4 paths
#define BC27    ((size_t)BC * 27)
#define BC9     ((size_t)BC * 9)
#define TILE_F  (TILE * 27)     // 1728 floats per (a or T2) tile
#define TILE_V4 (TILE_F / 4)    // 432 float4
#define NORM    (0.3333333333333333f)

__global__ __launch_bounds__(NTHREADS, 4)
void prod_einsum_kernel(const float* __restrict__ T1,
                        const float* __restrict__ T2,
                        float* __restrict__ out)
{
    __shared__ float t2s[TILE_F];        // [bc_local][27]
    __shared__ float t1s[4 * TILE_F];    // [a][bc_local][27]

    const int tid = threadIdx.x;
    const size_t bc0 = (size_t)blockIdx.x * TILE;

    // ---- Stage tiles: fully coalesced float4 loads (all bases 16B aligned:
    //      bc0*27*4 = blockIdx*6912 bytes; a-stride BC27*4 bytes, 16-divisible) ----
    {
        const float4* __restrict__ src2 = (const float4*)(T2 + bc0 * 27);
        float4* dst2 = (float4*)t2s;
        #pragma unroll
        for (int i = tid; i < TILE_V4; i += NTHREADS)
            dst2[i] = src2[i];

        #pragma unroll
        for (int a = 0; a < 4; ++a) {
            const float4* __restrict__ src1 =
                (const float4*)(T1 + (size_t)a * BC27 + bc0 * 27);
            float4* dst1 = (float4*)(t1s + a * TILE_F);
            #pragma unroll
            for (int i = tid; i < TILE_V4; i += NTHREADS)
                dst1[i] = src1[i];
        }
    }
    __syncthreads();

    // ---- Compute: thread = (a, bc_local). 27+27 smem floats -> 9 outputs. ----
    const int a   = tid >> 6;       // 0..3
    const int bcl = tid & 63;       // 0..63

    float r1[27], r2[27];
    {
        const float* __restrict__ p1 = t1s + a * TILE_F + bcl * 27;
        const float* __restrict__ p2 = t2s + bcl * 27;
        #pragma unroll
        for (int k = 0; k < 27; ++k) r1[k] = p1[k];
        #pragma unroll
        for (int k = 0; k < 27; ++k) r2[k] = p2[k];
    }

    float acc[9];
    #pragma unroll
    for (int d = 0; d < 3; ++d) {
        #pragma unroll
        for (int g = 0; g < 3; ++g) {
            float s = 0.0f;
            #pragma unroll
            for (int k = 0; k < 9; ++k)          // k = e*3 + f
                s = fmaf(r1[d * 9 + k], r2[k * 3 + g], s);
            acc[d * 3 + g] = s * NORM;
        }
    }

    // ---- Store: 9 contiguous floats per thread (36B runs; adjacent lanes
    //      adjacent runs -> sectors fully covered, merged in L2). ----
    float* __restrict__ o = out + (size_t)a * BC9 + (bc0 + bcl) * 9;
    #pragma unroll
    for (int i = 0; i < 9; ++i)
        o[i] = acc[i];
}

extern "C" void kernel_launch(void* const* d_in, const int* in_sizes, int n_in,
                              void* d_out, int out_size)
{
    const float* T1 = (const float*)d_in[0];
    const float* T2 = (const float*)d_in[1];
    float* out = (float*)d_out;

    const int nblocks = BC / TILE;   // 12288
    prod_einsum_kernel<<<nblocks, NTHREADS>>>(T1, T2, out);
}

// round 2
// speedup vs baseline: 1.4302x; 1.4302x over previous
#include <cuda_runtime.h>
#include <cstdint>

// ProdEinsumTC: out[a,b,c,d,g] = (1/3) * sum_{e,f} T1[a,b,c,d,e,f] * T2[b,c,e,f,g]
// T1: (4, 131072, 6, 27) fp32   T2: (131072, 6, 27) fp32   out: (4, 131072, 6, 9)
// Collapse (b,c) -> BC = 786432.
//
// R2 design: warp-autonomous tiles (8 bc per warp, 32 threads = 4 paths x 8 bc).
//  - cp.async.cg (LDGSTS, L2-only, no reg round-trip) stages 270 float4/warp.
//  - Only __syncwarp barriers -> warps overlap freely; no block-wide stalls.
//  - k-loop compute holds acc[9]+6 temps (~30 regs) -> 6 blocks/SM, 75% occ.
//  - Output staged in smem, written as STG.128 (perfect 128B coalescing).

#define BC        786432
#define BC27      ((size_t)BC * 27)
#define BC9       ((size_t)BC * 9)
#define WBC       8                 // bc pairs per warp
#define WARPS     8                 // warps per block
#define NTHREADS  (WARPS * 32)
#define WARP_F    (WBC * 27 * 5)    // 1080 floats per warp region (4xT1 + T2)
#define NORM      (0.3333333333333333f)

__device__ __forceinline__ void cp_async16(uint32_t dst, const void* src) {
    asm volatile("cp.async.cg.shared.global [%0], [%1], 16;\n"
                 :: "r"(dst), "l"(src));
}
__device__ __forceinline__ uint32_t smem_u32(const void* p) {
    uint32_t a;
    asm("{ .reg .u64 t; cvta.to.shared.u64 t, %1; cvt.u32.u64 %0, t; }"
        : "=r"(a) : "l"(p));
    return a;
}

__global__ __launch_bounds__(NTHREADS, 6)
void prod_einsum_kernel(const float* __restrict__ T1,
                        const float* __restrict__ T2,
                        float* __restrict__ out)
{
    __shared__ __align__(16) float smem[WARPS * WARP_F];   // 34560 B

    const int tid  = threadIdx.x;
    const int w    = tid >> 5;
    const int lane = tid & 31;

    float* const swarp = smem + w * WARP_F;
    const uint32_t sw_u32 = smem_u32(swarp);

    const size_t bc0 = ((size_t)blockIdx.x * WARPS + w) * WBC;

    // ---- Stage: 5 segments x 54 float4, all coalesced & 16B-aligned ----
    // Layout: [a=0..3][bcl][27] then [T2][bcl][27]
    #pragma unroll
    for (int a = 0; a < 4; ++a) {
        const float4* __restrict__ g1 =
            (const float4*)(T1 + (size_t)a * BC27 + bc0 * 27);
        cp_async16(sw_u32 + (a * 54 + lane) * 16, g1 + lane);
        if (lane < 22)
            cp_async16(sw_u32 + (a * 54 + 32 + lane) * 16, g1 + 32 + lane);
    }
    {
        const float4* __restrict__ g2 = (const float4*)(T2 + bc0 * 27);
        cp_async16(sw_u32 + (216 + lane) * 16, g2 + lane);
        if (lane < 22)
            cp_async16(sw_u32 + (216 + 32 + lane) * 16, g2 + 32 + lane);
    }
    asm volatile("cp.async.commit_group;\n");
    asm volatile("cp.async.wait_group 0;\n" ::: "memory");
    __syncwarp();

    // ---- Compute: lane = (a, bcl). 54 conflict-free LDS.32, 81 FMA ----
    const int a   = lane >> 3;     // 0..3
    const int bcl = lane & 7;      // 0..7

    const float* __restrict__ t1p = swarp + a * 216 + bcl * 27;  // [d][e][f]
    const float* __restrict__ t2p = swarp + 864 + bcl * 27;      // [e][f][g]

    float acc[9];
    #pragma unroll
    for (int i = 0; i < 9; ++i) acc[i] = 0.0f;

    #pragma unroll
    for (int k = 0; k < 9; ++k) {                 // k = e*3 + f
        const float b0 = t2p[k * 3 + 0];
        const float b1 = t2p[k * 3 + 1];
        const float b2 = t2p[k * 3 + 2];
        #pragma unroll
        for (int d = 0; d < 3; ++d) {
            const float av = t1p[d * 9 + k];
            acc[d * 3 + 0] = fmaf(av, b0, acc[d * 3 + 0]);
            acc[d * 3 + 1] = fmaf(av, b1, acc[d * 3 + 1]);
            acc[d * 3 + 2] = fmaf(av, b2, acc[d * 3 + 2]);
        }
    }

    // ---- Store: stage in smem, then STG.128 coalesced ----
    __syncwarp();                   // all compute reads of swarp done
    #pragma unroll
    for (int j = 0; j < 9; ++j)     // stride-9 STS.32: conflict-free
        swarp[lane * 9 + j] = acc[j] * NORM;
    __syncwarp();

    #pragma unroll
    for (int aa = 0; aa < 4; ++aa) {
        float4* __restrict__ o = (float4*)(out + (size_t)aa * BC9 + bc0 * 9);
        if (lane < 18)              // 72 floats = 18 float4 per path
            o[lane] = *(const float4*)(swarp + aa * 72 + lane * 4);
    }
}

extern "C" void kernel_launch(void* const* d_in, const int* in_sizes, int n_in,
                              void* d_out, int out_size)
{
    const float* T1 = (const float*)d_in[0];
    const float* T2 = (const float*)d_in[1];
    float* out = (float*)d_out;

    const int nblocks = BC / (WARPS * WBC);   // 12288
    prod_einsum_kernel<<<nblocks, NTHREADS>>>(T1, T2, out);
}

// round 3
// speedup vs baseline: 1.4307x; 1.0004x over previous
#include <cuda_runtime.h>
#include <cstdint>

// ProdEinsumTC: out[a,b,c,d,g] = (1/3) * sum_{e,f} T1[a,b,c,d,e,f] * T2[b,c,e,f,g]
// T1: (4, 131072, 6, 27) fp32   T2: (131072, 6, 27) fp32   out: (4, 131072, 6, 9)
//
// R3: R2 warp-autonomous structure + streaming cache policy.
//  - cp.async.cg with L2::evict_first policy (read-once lines die immediately)
//  - __stcs streaming stores (write-once lines drain promptly)
//  - everything else identical to the 80.6us R2 kernel.

#define BC        786432
#define BC27      ((size_t)BC * 27)
#define BC9       ((size_t)BC * 9)
#define WBC       8                 // bc pairs per warp
#define WARPS     8                 // warps per block
#define NTHREADS  (WARPS * 32)
#define WARP_F    (WBC * 27 * 5)    // 1080 floats per warp region (4xT1 + T2)
#define NORM      (0.3333333333333333f)

__device__ __forceinline__ void cp_async16_ef(uint32_t dst, const void* src,
                                              uint64_t pol) {
    asm volatile("cp.async.cg.shared.global.L2::cache_hint [%0], [%1], 16, %2;\n"
                 :: "r"(dst), "l"(src), "l"(pol));
}
__device__ __forceinline__ uint32_t smem_u32(const void* p) {
    uint32_t a;
    asm("{ .reg .u64 t; cvta.to.shared.u64 t, %1; cvt.u32.u64 %0, t; }"
        : "=r"(a) : "l"(p));
    return a;
}

__global__ __launch_bounds__(NTHREADS, 6)
void prod_einsum_kernel(const float* __restrict__ T1,
                        const float* __restrict__ T2,
                        float* __restrict__ out)
{
    __shared__ __align__(16) float smem[WARPS * WARP_F];   // 34560 B

    const int tid  = threadIdx.x;
    const int w    = tid >> 5;
    const int lane = tid & 31;

    float* const swarp = smem + w * WARP_F;
    const uint32_t sw_u32 = smem_u32(swarp);

    const size_t bc0 = ((size_t)blockIdx.x * WARPS + w) * WBC;

    uint64_t pol;
    asm("createpolicy.fractional.L2::evict_first.b64 %0, 1.0;" : "=l"(pol));

    // ---- Stage: 5 segments x 54 float4, coalesced, 16B aligned, evict-first ----
    #pragma unroll
    for (int a = 0; a < 4; ++a) {
        const float4* __restrict__ g1 =
            (const float4*)(T1 + (size_t)a * BC27 + bc0 * 27);
        cp_async16_ef(sw_u32 + (a * 54 + lane) * 16, g1 + lane, pol);
        if (lane < 22)
            cp_async16_ef(sw_u32 + (a * 54 + 32 + lane) * 16, g1 + 32 + lane, pol);
    }
    {
        const float4* __restrict__ g2 = (const float4*)(T2 + bc0 * 27);
        cp_async16_ef(sw_u32 + (216 + lane) * 16, g2 + lane, pol);
        if (lane < 22)
            cp_async16_ef(sw_u32 + (216 + 32 + lane) * 16, g2 + 32 + lane, pol);
    }
    asm volatile("cp.async.commit_group;\n");
    asm volatile("cp.async.wait_group 0;\n" ::: "memory");
    __syncwarp();

    // ---- Compute: lane = (a, bcl). 54 conflict-free LDS.32, 81 FMA ----
    const int a   = lane >> 3;     // 0..3
    const int bcl = lane & 7;      // 0..7

    const float* __restrict__ t1p = swarp + a * 216 + bcl * 27;  // [d][e][f]
    const float* __restrict__ t2p = swarp + 864 + bcl * 27;      // [e][f][g]

    float acc[9];
    #pragma unroll
    for (int i = 0; i < 9; ++i) acc[i] = 0.0f;

    #pragma unroll
    for (int k = 0; k < 9; ++k) {                 // k = e*3 + f
        const float b0 = t2p[k * 3 + 0];
        const float b1 = t2p[k * 3 + 1];
        const float b2 = t2p[k * 3 + 2];
        #pragma unroll
        for (int d = 0; d < 3; ++d) {
            const float av = t1p[d * 9 + k];
            acc[d * 3 + 0] = fmaf(av, b0, acc[d * 3 + 0]);
            acc[d * 3 + 1] = fmaf(av, b1, acc[d * 3 + 1]);
            acc[d * 3 + 2] = fmaf(av, b2, acc[d * 3 + 2]);
        }
    }

    // ---- Store: stage in smem, then streaming STG.128 (evict-first) ----
    __syncwarp();                   // all compute reads of swarp done
    #pragma unroll
    for (int j = 0; j < 9; ++j)     // stride-9 STS.32: conflict-free
        swarp[lane * 9 + j] = acc[j] * NORM;
    __syncwarp();

    #pragma unroll
    for (int aa = 0; aa < 4; ++aa) {
        float4* __restrict__ o = (float4*)(out + (size_t)aa * BC9 + bc0 * 9);
        if (lane < 18)              // 72 floats = 18 float4 per path
            __stcs(o + lane, *(const float4*)(swarp + aa * 72 + lane * 4));
    }
}

extern "C" void kernel_launch(void* const* d_in, const int* in_sizes, int n_in,
                              void* d_out, int out_size)
{
    const float* T1 = (const float*)d_in[0];
    const float* T2 = (const float*)d_in[1];
    float* out = (float*)d_out;

    const int nblocks = BC / (WARPS * WBC);   // 12288
    prod_einsum_kernel<<<nblocks, NTHREADS>>>(T1, T2, out);
}